// round 10
// baseline (speedup 1.0000x reference)
#include <cuda_runtime.h>
#include <cuda_bf16.h>
#include <cstdint>

// ---------------------------------------------------------------------------
// MambaBlock: B=4, L=512, d_model=128, d_inner=d_state=256, rows = 2048
//   xproj = x @ W_in ; delta/Bv/Cv = xs @ {Wd,Wb,Wc} (fused, xb=Bv*xs epilogue)
//   chunked scan (NC=8 x CT=64), d-multiplicity m=4: each warp owns FOUR
//   d-channels; cv/xb loads shared by all four. passA local scan, passC
//   prefix-combine + correction + silu gate ; out = g @ W_out
// kernel_launch performs kernel launches ONLY (graph-capture safe).
// ---------------------------------------------------------------------------

#define ROWS 2048
#define DI   256
#define DM   128
#define NC   8
#define CT   64

__device__ float g_xproj[ROWS * 512];
__device__ float g_delta[ROWS * DI];
__device__ float g_Bv[ROWS * DI];     // xb = Bv * xs after k_dbc
__device__ float g_Cv[ROWS * DI];
__device__ float g_y[ROWS * DI];
__device__ float g_state[NC * 4 * DI * DI];   // [c][b][d][n]
__device__ float g_dsum[NC * 4 * DI];         // [c][b][d]

__device__ __forceinline__ float ex2f(float x) {
    float r;
    asm("ex2.approx.ftz.f32 %0, %1;" : "=f"(r) : "f"(x));
    return r;
}

__device__ __forceinline__ void load8(float* r, const float* __restrict__ p) {
    float4 u = *(const float4*)p;
    float4 v = *(const float4*)(p + 4);
    r[0] = u.x; r[1] = u.y; r[2] = u.z; r[3] = u.w;
    r[4] = v.x; r[5] = v.y; r[6] = v.z; r[7] = v.w;
}
__device__ __forceinline__ void store8(float* __restrict__ p, const float* r) {
    *(float4*)p       = make_float4(r[0], r[1], r[2], r[3]);
    *(float4*)(p + 4) = make_float4(r[4], r[5], r[6], r[7]);
}

// ---------------------------------------------------------------------------
// fp32 tiled GEMM body, double-buffered smem: 64x64 tile, BK=16, 256 thr.
// ---------------------------------------------------------------------------
__device__ __forceinline__ void gemm_body(
    const float* __restrict__ A, const float* __restrict__ B, float* __restrict__ C,
    int K, int lda, int ldb, int ldc, bool mul_xs)
{
    __shared__ float As[2][16][64];
    __shared__ float Bs[2][16][64];

    const int tx = threadIdx.x & 15;
    const int ty = threadIdx.x >> 4;
    const int rowBase = blockIdx.y * 64;
    const int colBase = blockIdx.x * 64;

    const int lr = threadIdx.x >> 2;
    const int lk = (threadIdx.x & 3) << 2;
    const int bk = threadIdx.x >> 4;
    const int bc = (threadIdx.x & 15) << 2;

    const float* Aptr = A + (size_t)(rowBase + lr) * lda + lk;
    const float* Bptr = B + (size_t)bk * ldb + colBase + bc;

    float acc[4][4] = {};
    const int nT = K >> 4;

    float4 av = *(const float4*)Aptr;
    float4 bv = *(const float4*)Bptr;

    for (int kt = 0; kt < nT; kt++) {
        const int p = kt & 1;
        As[p][lk + 0][lr] = av.x;
        As[p][lk + 1][lr] = av.y;
        As[p][lk + 2][lr] = av.z;
        As[p][lk + 3][lr] = av.w;
        *(float4*)&Bs[p][bk][bc] = bv;
        __syncthreads();

        if (kt + 1 < nT) {
            av = *(const float4*)(Aptr + (kt + 1) * 16);
            bv = *(const float4*)(Bptr + (size_t)(kt + 1) * 16 * ldb);
        }

        #pragma unroll
        for (int k = 0; k < 16; k++) {
            float4 a4 = *(const float4*)&As[p][k][ty << 2];
            float4 b4 = *(const float4*)&Bs[p][k][tx << 2];
            acc[0][0] += a4.x * b4.x; acc[0][1] += a4.x * b4.y;
            acc[0][2] += a4.x * b4.z; acc[0][3] += a4.x * b4.w;
            acc[1][0] += a4.y * b4.x; acc[1][1] += a4.y * b4.y;
            acc[1][2] += a4.y * b4.z; acc[1][3] += a4.y * b4.w;
            acc[2][0] += a4.z * b4.x; acc[2][1] += a4.z * b4.y;
            acc[2][2] += a4.z * b4.z; acc[2][3] += a4.z * b4.w;
            acc[3][0] += a4.w * b4.x; acc[3][1] += a4.w * b4.y;
            acc[3][2] += a4.w * b4.z; acc[3][3] += a4.w * b4.w;
        }
        __syncthreads();
    }

    #pragma unroll
    for (int i = 0; i < 4; i++) {
        const int row = rowBase + (ty << 2) + i;
        float4 v = make_float4(acc[i][0], acc[i][1], acc[i][2], acc[i][3]);
        if (mul_xs) {
            float4 xs4 = *(const float4*)(g_xproj + (size_t)row * 512 + colBase + (tx << 2));
            v.x *= xs4.x; v.y *= xs4.y; v.z *= xs4.z; v.w *= xs4.w;
        }
        *(float4*)(C + (size_t)row * ldc + colBase + (tx << 2)) = v;
    }
}

__global__ void __launch_bounds__(256) k_in_proj(const float* __restrict__ x,
                                                 const float* __restrict__ W_in) {
    gemm_body(x, W_in, g_xproj, DM, DM, 512, 512, false);
}

__global__ void __launch_bounds__(256) k_dbc(const float* __restrict__ Wd,
                                             const float* __restrict__ Wb,
                                             const float* __restrict__ Wc) {
    const float* W = (blockIdx.z == 0) ? Wd : ((blockIdx.z == 1) ? Wb : Wc);
    float* C = (blockIdx.z == 0) ? g_delta : ((blockIdx.z == 1) ? g_Bv : g_Cv);
    gemm_body(g_xproj, W, C, DI, 512, DI, DI, blockIdx.z == 1);
}

__global__ void __launch_bounds__(256) k_out_proj(const float* __restrict__ W_out,
                                                  float* __restrict__ out) {
    __shared__ float As[2][16][32];
    __shared__ float Bs[2][16][64];

    const int tx = threadIdx.x & 15;
    const int ty = threadIdx.x >> 4;
    const int rowBase = blockIdx.y * 32;
    const int colBase = blockIdx.x * 64;

    const int lr = threadIdx.x >> 3;
    const int lk = (threadIdx.x & 7) << 1;
    const int bk = threadIdx.x >> 4;
    const int bc = (threadIdx.x & 15) << 2;

    const float* Aptr = g_y + (size_t)(rowBase + lr) * DI + lk;
    const float* Bptr = W_out + (size_t)bk * DM + colBase + bc;

    float acc[2][4] = {};
    const int nT = DI >> 4;

    float2 av = *(const float2*)Aptr;
    float4 bv = *(const float4*)Bptr;

    for (int kt = 0; kt < nT; kt++) {
        const int p = kt & 1;
        As[p][lk + 0][lr] = av.x;
        As[p][lk + 1][lr] = av.y;
        *(float4*)&Bs[p][bk][bc] = bv;
        __syncthreads();

        if (kt + 1 < nT) {
            av = *(const float2*)(Aptr + (kt + 1) * 16);
            bv = *(const float4*)(Bptr + (size_t)(kt + 1) * 16 * DM);
        }

        #pragma unroll
        for (int k = 0; k < 16; k++) {
            float a0 = As[p][k][(ty << 1) + 0];
            float a1 = As[p][k][(ty << 1) + 1];
            float4 b4 = *(const float4*)&Bs[p][k][tx << 2];
            acc[0][0] += a0 * b4.x; acc[0][1] += a0 * b4.y;
            acc[0][2] += a0 * b4.z; acc[0][3] += a0 * b4.w;
            acc[1][0] += a1 * b4.x; acc[1][1] += a1 * b4.y;
            acc[1][2] += a1 * b4.z; acc[1][3] += a1 * b4.w;
        }
        __syncthreads();
    }

    #pragma unroll
    for (int i = 0; i < 2; i++) {
        float4 v = make_float4(acc[i][0], acc[i][1], acc[i][2], acc[i][3]);
        *(float4*)(out + (size_t)(rowBase + (ty << 1) + i) * DM + colBase + (tx << 2)) = v;
    }
}

// ---------------------------------------------------------------------------
// treduce4: p[0..3] hold this lane's partials for 4 consecutive steps.
// After: EVERY lane holds the full 32-lane sum for step (lane & 3).
// 6 SHFL total.
// ---------------------------------------------------------------------------
__device__ __forceinline__ void treduce4(float* p, int lane) {
    #pragma unroll
    for (int k = 0; k < 4; k += 2) {                 // level 1: step bit0 <- lane bit0
        float mine  = (lane & 1) ? p[k] : p[k + 1];
        float other = __shfl_xor_sync(0xffffffffu, mine, 1);
        float keep  = (lane & 1) ? p[k + 1] : p[k];
        p[k >> 1] = keep + other;
    }
    {                                                // level 2: step bit1 <- lane bit1
        float mine  = (lane & 2) ? p[0] : p[1];
        float other = __shfl_xor_sync(0xffffffffu, mine, 2);
        float keep  = (lane & 2) ? p[1] : p[0];
        p[0] = keep + other;
    }
    p[0] += __shfl_xor_sync(0xffffffffu, p[0], 4);
    p[0] += __shfl_xor_sync(0xffffffffu, p[0], 8);
    p[0] += __shfl_xor_sync(0xffffffffu, p[0], 16);
}

// ---------------------------------------------------------------------------
// Pass A (m=4): chunk-local scan. Grid (16, NC, 4) = 512 CTAs, 128 threads.
// Warp owns FOUR contiguous d-channels (d0..d0+3); one cv/xb load8 per step
// feeds 32 cell-updates per lane. dv loaded as one broadcast float4.
// Groups of 4 steps -> treduce4 per d -> single 16-lane store.
// ---------------------------------------------------------------------------
__global__ void __launch_bounds__(128) scan_passA(const float* __restrict__ A)
{
    const int c    = blockIdx.y;
    const int b    = blockIdx.z;
    const int wid  = threadIdx.x >> 5;
    const int lane = threadIdx.x & 31;
    const int d0   = blockIdx.x * 16 + wid * 4;
    const int no   = lane << 3;
    const float LOG2E = 1.4426950408889634f;

    float a0[8], a1[8], a2[8], a3[8];
    load8(a0, A + (size_t)(d0 + 0) * 256 + no);
    load8(a1, A + (size_t)(d0 + 1) * 256 + no);
    load8(a2, A + (size_t)(d0 + 2) * 256 + no);
    load8(a3, A + (size_t)(d0 + 3) * 256 + no);
    #pragma unroll
    for (int j = 0; j < 8; j++) {
        a0[j] *= LOG2E; a1[j] *= LOG2E; a2[j] *= LOG2E; a3[j] *= LOG2E;
    }

    float s0[8] = {}, s1[8] = {}, s2[8] = {}, s3[8] = {};
    float4 ds = make_float4(0.f, 0.f, 0.f, 0.f);

    const int row0 = b * 512 + c * CT;
    const float* __restrict__ xbp = g_Bv    + (size_t)row0 * 256 + no;
    const float* __restrict__ cvp = g_Cv    + (size_t)row0 * 256 + no;
    const float* __restrict__ dvp = g_delta + (size_t)row0 * 256 + d0;

    float xb[2][8], cv[2][8];
    float4 dvr[2];
    load8(xb[0], xbp); load8(cv[0], cvp);
    dvr[0] = *(const float4*)dvp;

    float p0[4], p1[4], p2[4], p3[4];

    for (int g = 0; g < CT / 4; g++) {
        #pragma unroll
        for (int t4 = 0; t4 < 4; t4++) {
            const int t  = g * 4 + t4;
            const int tp = (t + 1 < CT) ? (t + 1) : t;
            const int sp = (t + 1) & 1;
            load8(xb[sp], xbp + (size_t)tp * 256);
            load8(cv[sp], cvp + (size_t)tp * 256);
            dvr[sp] = *(const float4*)(dvp + (size_t)tp * 256);

            const int sc = t & 1;
            const float4 dv = dvr[sc];
            ds.x += dv.x; ds.y += dv.y; ds.z += dv.z; ds.w += dv.w;
            float acc0 = 0.f, acc1 = 0.f, acc2 = 0.f, acc3 = 0.f;
            #pragma unroll
            for (int j = 0; j < 8; j++) {
                const float bx = xb[sc][j];
                const float cj = cv[sc][j];
                s0[j] = fmaf(ex2f(dv.x * a0[j]), s0[j], dv.x * bx);
                acc0  = fmaf(s0[j], cj, acc0);
                s1[j] = fmaf(ex2f(dv.y * a1[j]), s1[j], dv.y * bx);
                acc1  = fmaf(s1[j], cj, acc1);
                s2[j] = fmaf(ex2f(dv.z * a2[j]), s2[j], dv.z * bx);
                acc2  = fmaf(s2[j], cj, acc2);
                s3[j] = fmaf(ex2f(dv.w * a3[j]), s3[j], dv.w * bx);
                acc3  = fmaf(s3[j], cj, acc3);
            }
            p0[t4] = acc0; p1[t4] = acc1; p2[t4] = acc2; p3[t4] = acc3;
        }
        treduce4(p0, lane);
        treduce4(p1, lane);
        treduce4(p2, lane);
        treduce4(p3, lane);
        if (lane < 16) {
            const int dd = lane >> 2;
            const int st = lane & 3;
            float v = (dd == 0) ? p0[0] : (dd == 1) ? p1[0] : (dd == 2) ? p2[0] : p3[0];
            g_y[(size_t)(row0 + g * 4 + st) * 256 + d0 + dd] = v;
        }
    }

    const size_t sb = ((size_t)(c * 4 + b) * 256 + d0) * 256 + no;
    store8(g_state + sb,           s0);
    store8(g_state + sb + 256,     s1);
    store8(g_state + sb + 512,     s2);
    store8(g_state + sb + 768,     s3);
    if (lane == 0)
        *(float4*)(g_dsum + (c * 4 + b) * 256 + d0) = ds;
}

// ---------------------------------------------------------------------------
// Pass C (m=4): prefix combine + correction + SiLU gate. Grid (16, NC, 4),
// 128 threads. Warp owns four d-channels; cv shared across all four.
// ---------------------------------------------------------------------------
__global__ void __launch_bounds__(128) scan_passC(const float* __restrict__ A)
{
    const int c    = blockIdx.y;
    const int b    = blockIdx.z;
    const int wid  = threadIdx.x >> 5;
    const int lane = threadIdx.x & 31;
    const int d0   = blockIdx.x * 16 + wid * 4;
    const int no   = lane << 3;
    const float LOG2E = 1.4426950408889634f;

    float a0[8], a1[8], a2[8], a3[8];
    load8(a0, A + (size_t)(d0 + 0) * 256 + no);
    load8(a1, A + (size_t)(d0 + 1) * 256 + no);
    load8(a2, A + (size_t)(d0 + 2) * 256 + no);
    load8(a3, A + (size_t)(d0 + 3) * 256 + no);
    #pragma unroll
    for (int j = 0; j < 8; j++) {
        a0[j] *= LOG2E; a1[j] *= LOG2E; a2[j] *= LOG2E; a3[j] *= LOG2E;
    }

    // prefix combine: w = incoming state for chunk c, all four d's
    float w0[8] = {}, w1[8] = {}, w2[8] = {}, w3[8] = {};
    for (int cp = 0; cp < c; cp++) {
        const size_t sb = ((size_t)(cp * 4 + b) * 256 + d0) * 256 + no;
        const float4 dsv = *(const float4*)(g_dsum + (cp * 4 + b) * 256 + d0);
        float e[8];
        load8(e, g_state + sb);
        #pragma unroll
        for (int j = 0; j < 8; j++) w0[j] = fmaf(ex2f(dsv.x * a0[j]), w0[j], e[j]);
        load8(e, g_state + sb + 256);
        #pragma unroll
        for (int j = 0; j < 8; j++) w1[j] = fmaf(ex2f(dsv.y * a1[j]), w1[j], e[j]);
        load8(e, g_state + sb + 512);
        #pragma unroll
        for (int j = 0; j < 8; j++) w2[j] = fmaf(ex2f(dsv.z * a2[j]), w2[j], e[j]);
        load8(e, g_state + sb + 768);
        #pragma unroll
        for (int j = 0; j < 8; j++) w3[j] = fmaf(ex2f(dsv.w * a3[j]), w3[j], e[j]);
    }

    const int row0 = b * 512 + c * CT;
    const float* __restrict__ cvp = g_Cv    + (size_t)row0 * 256 + no;
    const float* __restrict__ dvp = g_delta + (size_t)row0 * 256 + d0;
    const float* __restrict__ zvp = g_xproj + (size_t)row0 * 512 + 256 + d0;
    float*       __restrict__ yp  = g_y     + (size_t)row0 * 256 + d0;

    float cv[2][8];
    float4 dvr[2];
    load8(cv[0], cvp);
    dvr[0] = *(const float4*)dvp;

    float p0[4], p1[4], p2[4], p3[4];
    const int st = lane & 3;
    const int dd = lane >> 2;

    for (int g = 0; g < CT / 4; g++) {
        // prefetch this group's gate operands (lane -> (step, d) pair)
        float zq = 0.f, yq = 0.f;
        if (lane < 16) {
            zq = zvp[(size_t)(g * 4 + st) * 512 + dd];
            yq = yp[(size_t)(g * 4 + st) * 256 + dd];
        }

        #pragma unroll
        for (int t4 = 0; t4 < 4; t4++) {
            const int t  = g * 4 + t4;
            const int tp = (t + 1 < CT) ? (t + 1) : t;
            const int sp = (t + 1) & 1;
            load8(cv[sp], cvp + (size_t)tp * 256);
            dvr[sp] = *(const float4*)(dvp + (size_t)tp * 256);

            const int sc = t & 1;
            const float4 dv = dvr[sc];
            float acc0 = 0.f, acc1 = 0.f, acc2 = 0.f, acc3 = 0.f;
            #pragma unroll
            for (int j = 0; j < 8; j++) {
                const float cj = cv[sc][j];
                w0[j] *= ex2f(dv.x * a0[j]);
                acc0 = fmaf(w0[j], cj, acc0);
                w1[j] *= ex2f(dv.y * a1[j]);
                acc1 = fmaf(w1[j], cj, acc1);
                w2[j] *= ex2f(dv.z * a2[j]);
                acc2 = fmaf(w2[j], cj, acc2);
                w3[j] *= ex2f(dv.w * a3[j]);
                acc3 = fmaf(w3[j], cj, acc3);
            }
            p0[t4] = acc0; p1[t4] = acc1; p2[t4] = acc2; p3[t4] = acc3;
        }
        treduce4(p0, lane);
        treduce4(p1, lane);
        treduce4(p2, lane);
        treduce4(p3, lane);
        if (lane < 16) {
            float v = (dd == 0) ? p0[0] : (dd == 1) ? p1[0] : (dd == 2) ? p2[0] : p3[0];
            const float sg = 1.f / (1.f + __expf(-zq));
            yp[(size_t)(g * 4 + st) * 256 + dd] = (yq + v) * (zq * sg);
        }
    }
}

extern "C" void kernel_launch(void* const* d_in, const int* in_sizes, int n_in,
                              void* d_out, int out_size)
{
    const float* x       = (const float*)d_in[0];
    const float* W_in    = (const float*)d_in[1];
    const float* W_delta = (const float*)d_in[2];
    const float* W_B     = (const float*)d_in[3];
    const float* W_C     = (const float*)d_in[4];
    const float* W_out   = (const float*)d_in[5];
    const float* A       = (const float*)d_in[6];
    float* out = (float*)d_out;

    k_in_proj <<<dim3(8, 32),     256>>>(x, W_in);
    k_dbc     <<<dim3(4, 32, 3),  256>>>(W_delta, W_B, W_C);
    scan_passA<<<dim3(16, NC, 4), 128>>>(A);
    scan_passC<<<dim3(16, NC, 4), 128>>>(A);
    k_out_proj<<<dim3(2, 64),     256>>>(W_out, out);
}

// round 11
// speedup vs baseline: 1.1875x; 1.1875x over previous
#include <cuda_runtime.h>
#include <cuda_bf16.h>
#include <cstdint>

// ---------------------------------------------------------------------------
// MambaBlock: B=4, L=512, d_model=128, d_inner=d_state=256, rows = 2048
//   GEMMs on TF32 tensor cores (mma.m16n8k8), fp32 accumulate:
//     xproj = x @ W_in ; delta/Bv/Cv = xs @ {Wd,Wb,Wc} (xb=Bv*xs epilogue)
//     out = g @ W_out
//   chunked scan (NC=8 x CT=64), d-multiplicity m=2 (R9 measured config):
//     passA local scan, passC prefix-combine + correction + silu gate
// kernel_launch performs kernel launches ONLY (graph-capture safe).
// ---------------------------------------------------------------------------

#define ROWS 2048
#define DI   256
#define DM   128
#define NC   8
#define CT   64

__device__ float g_xproj[ROWS * 512];
__device__ float g_delta[ROWS * DI];
__device__ float g_Bv[ROWS * DI];     // xb = Bv * xs after k_dbc
__device__ float g_Cv[ROWS * DI];
__device__ float g_y[ROWS * DI];
__device__ float g_state[NC * 4 * DI * DI];   // [c][b][d][n]
__device__ float g_dsum[NC * 4 * DI];         // [c][b][d]

__device__ __forceinline__ float ex2f(float x) {
    float r;
    asm("ex2.approx.ftz.f32 %0, %1;" : "=f"(r) : "f"(x));
    return r;
}
__device__ __forceinline__ uint32_t tf32cvt(float f) {
    uint32_t u;
    asm("cvt.rna.tf32.f32 %0, %1;" : "=r"(u) : "f"(f));
    return u;
}

__device__ __forceinline__ void load8(float* r, const float* __restrict__ p) {
    float4 u = *(const float4*)p;
    float4 v = *(const float4*)(p + 4);
    r[0] = u.x; r[1] = u.y; r[2] = u.z; r[3] = u.w;
    r[4] = v.x; r[5] = v.y; r[6] = v.z; r[7] = v.w;
}
__device__ __forceinline__ void store8(float* __restrict__ p, const float* r) {
    *(float4*)p       = make_float4(r[0], r[1], r[2], r[3]);
    *(float4*)(p + 4) = make_float4(r[4], r[5], r[6], r[7]);
}

__device__ __forceinline__ void mma_tf32(float* acc, const uint32_t* a, uint32_t b0, uint32_t b1) {
    asm volatile(
        "mma.sync.aligned.m16n8k8.row.col.f32.tf32.tf32.f32 "
        "{%0,%1,%2,%3},{%4,%5,%6,%7},{%8,%9},{%0,%1,%2,%3};\n"
        : "+f"(acc[0]), "+f"(acc[1]), "+f"(acc[2]), "+f"(acc[3])
        : "r"(a[0]), "r"(a[1]), "r"(a[2]), "r"(a[3]), "r"(b0), "r"(b1));
}

// ---------------------------------------------------------------------------
// TF32 tensor-core GEMM: C[M,N] = A[M,K] @ B[K,N], row-major. CTA tile
// TM x 64 (TM=64: 256 thr, 8 warps 4Mx2N; TM=32: 128 thr, 4 warps 2Mx2N).
// Warp tile 16x32 = 4 x m16n8k8. Double-buffered smem; operands converted
// to tf32 at staging. As layout [m][k] stride 20, Bs [k][n] stride 72
// (both conflict-free for the fragment gathers).
// MUL_XS: multiply output by g_xproj[row, col] (xs) before store.
// ---------------------------------------------------------------------------
template<int TM, bool MUL_XS>
__device__ __forceinline__ void gemm_mma(
    const float* __restrict__ A, const float* __restrict__ B, float* __restrict__ C,
    int K, int lda, int ldb, int ldc)
{
    constexpr int WM = TM / 16;              // warps along M
    __shared__ uint32_t As[2][TM][20];
    __shared__ uint32_t Bs[2][16][72];

    const int tid   = threadIdx.x;
    const int lane  = tid & 31;
    const int wid   = tid >> 5;
    const int warpM = wid % WM;
    const int warpN = wid / WM;
    const int lane4 = lane & 3;
    const int laneD = lane >> 2;

    const int rowBase = blockIdx.y * TM + warpM * 16;
    const int colBase = blockIdx.x * 64 + warpN * 32;
    const int mL      = warpM * 16 + laneD;          // tile-local A row
    const int nL      = warpN * 32 + laneD;          // tile-local B col base

    // A loader: 4 floats/thread (TM*16 elems)
    const int ar = tid >> 2;                         // 0..TM-1
    const int ak = (tid & 3) << 2;                   // 0,4,8,12
    // B loader: 16x64 elems
    const int bkB = (TM == 64) ? (tid >> 4) : (tid >> 3);
    const int bcB = (TM == 64) ? ((tid & 15) << 2) : ((tid & 7) << 3);

    const float* Aptr = A + (size_t)(blockIdx.y * TM + ar) * lda + ak;
    const float* Bptr = B + (size_t)bkB * ldb + blockIdx.x * 64 + bcB;

    float acc[4][4] = {};
    const int nT = K >> 4;

    float4 av  = *(const float4*)Aptr;
    float4 bv0 = *(const float4*)Bptr;
    float4 bv1 = (TM == 32) ? *(const float4*)(Bptr + 4) : make_float4(0, 0, 0, 0);

    for (int kt = 0; kt < nT; kt++) {
        const int p = kt & 1;
        As[p][ar][ak + 0] = tf32cvt(av.x);
        As[p][ar][ak + 1] = tf32cvt(av.y);
        As[p][ar][ak + 2] = tf32cvt(av.z);
        As[p][ar][ak + 3] = tf32cvt(av.w);
        Bs[p][bkB][bcB + 0] = tf32cvt(bv0.x);
        Bs[p][bkB][bcB + 1] = tf32cvt(bv0.y);
        Bs[p][bkB][bcB + 2] = tf32cvt(bv0.z);
        Bs[p][bkB][bcB + 3] = tf32cvt(bv0.w);
        if (TM == 32) {
            Bs[p][bkB][bcB + 4] = tf32cvt(bv1.x);
            Bs[p][bkB][bcB + 5] = tf32cvt(bv1.y);
            Bs[p][bkB][bcB + 6] = tf32cvt(bv1.z);
            Bs[p][bkB][bcB + 7] = tf32cvt(bv1.w);
        }
        __syncthreads();

        if (kt + 1 < nT) {
            av  = *(const float4*)(Aptr + (kt + 1) * 16);
            bv0 = *(const float4*)(Bptr + (size_t)(kt + 1) * 16 * ldb);
            if (TM == 32) bv1 = *(const float4*)(Bptr + (size_t)(kt + 1) * 16 * ldb + 4);
        }

        #pragma unroll
        for (int k0 = 0; k0 < 16; k0 += 8) {
            uint32_t af[4];
            af[0] = As[p][mL][k0 + lane4];
            af[1] = As[p][mL + 8][k0 + lane4];
            af[2] = As[p][mL][k0 + lane4 + 4];
            af[3] = As[p][mL + 8][k0 + lane4 + 4];
            #pragma unroll
            for (int s = 0; s < 4; s++) {
                uint32_t b0 = Bs[p][k0 + lane4][nL + s * 8];
                uint32_t b1 = Bs[p][k0 + lane4 + 4][nL + s * 8];
                mma_tf32(acc[s], af, b0, b1);
            }
        }
        __syncthreads();
    }

    const int row0 = rowBase + laneD;
    const int row1 = row0 + 8;
    #pragma unroll
    for (int s = 0; s < 4; s++) {
        const int col = colBase + s * 8 + 2 * lane4;
        float2 v0 = make_float2(acc[s][0], acc[s][1]);
        float2 v1 = make_float2(acc[s][2], acc[s][3]);
        if (MUL_XS) {
            float2 x0 = *(const float2*)(g_xproj + (size_t)row0 * 512 + col);
            float2 x1 = *(const float2*)(g_xproj + (size_t)row1 * 512 + col);
            v0.x *= x0.x; v0.y *= x0.y;
            v1.x *= x1.x; v1.y *= x1.y;
        }
        *(float2*)(C + (size_t)row0 * ldc + col) = v0;
        *(float2*)(C + (size_t)row1 * ldc + col) = v1;
    }
}

__global__ void __launch_bounds__(256) k_in_proj(const float* __restrict__ x,
                                                 const float* __restrict__ W_in) {
    gemm_mma<64, false>(x, W_in, g_xproj, DM, DM, 512, 512);
}

__global__ void __launch_bounds__(256) k_dbc(const float* __restrict__ Wd,
                                             const float* __restrict__ Wb,
                                             const float* __restrict__ Wc) {
    if (blockIdx.z == 0)      gemm_mma<64, false>(g_xproj, Wd, g_delta, DI, 512, DI, DI);
    else if (blockIdx.z == 1) gemm_mma<64, true >(g_xproj, Wb, g_Bv,    DI, 512, DI, DI);
    else                      gemm_mma<64, false>(g_xproj, Wc, g_Cv,    DI, 512, DI, DI);
}

__global__ void __launch_bounds__(128) k_out_proj(const float* __restrict__ W_out,
                                                  float* __restrict__ out) {
    gemm_mma<32, false>(g_y, W_out, out, DI, DI, DM, DM);
}

// ---------------------------------------------------------------------------
// treduce8: p[0..7] per-lane partials for 8 steps -> every lane holds the
// full 32-lane sum for step (lane & 7). 9 SHFL.
// ---------------------------------------------------------------------------
__device__ __forceinline__ void treduce8(float* p, int lane) {
    #pragma unroll
    for (int k = 0; k < 8; k += 2) {
        float mine  = (lane & 1) ? p[k] : p[k + 1];
        float other = __shfl_xor_sync(0xffffffffu, mine, 1);
        float keep  = (lane & 1) ? p[k + 1] : p[k];
        p[k >> 1] = keep + other;
    }
    #pragma unroll
    for (int k = 0; k < 4; k += 2) {
        float mine  = (lane & 2) ? p[k] : p[k + 1];
        float other = __shfl_xor_sync(0xffffffffu, mine, 2);
        float keep  = (lane & 2) ? p[k + 1] : p[k];
        p[k >> 1] = keep + other;
    }
    {
        float mine  = (lane & 4) ? p[0] : p[1];
        float other = __shfl_xor_sync(0xffffffffu, mine, 4);
        float keep  = (lane & 4) ? p[1] : p[0];
        p[0] = keep + other;
    }
    p[0] += __shfl_xor_sync(0xffffffffu, p[0], 8);
    p[0] += __shfl_xor_sync(0xffffffffu, p[0], 16);
}

// ---------------------------------------------------------------------------
// Pass A (m=2, R9 config): chunk-local scan. Grid (32, NC, 4), 128 threads.
// Warp owns TWO d-channels; cv/xb loads shared by both.
// ---------------------------------------------------------------------------
__global__ void __launch_bounds__(128) scan_passA(const float* __restrict__ A)
{
    const int c    = blockIdx.y;
    const int b    = blockIdx.z;
    const int wid  = threadIdx.x >> 5;
    const int lane = threadIdx.x & 31;
    const int d0   = blockIdx.x * 8 + wid * 2;
    const int no   = lane << 3;
    const float LOG2E = 1.4426950408889634f;

    float a0[8], a1[8];
    load8(a0, A + (size_t)d0 * 256 + no);
    load8(a1, A + (size_t)(d0 + 1) * 256 + no);
    #pragma unroll
    for (int j = 0; j < 8; j++) { a0[j] *= LOG2E; a1[j] *= LOG2E; }

    float s0[8] = {}, s1[8] = {};
    float ds0 = 0.f, ds1 = 0.f;

    const int row0 = b * 512 + c * CT;
    const float* __restrict__ xbp = g_Bv    + (size_t)row0 * 256 + no;
    const float* __restrict__ cvp = g_Cv    + (size_t)row0 * 256 + no;
    const float* __restrict__ dvp = g_delta + (size_t)row0 * 256;

    float xb[2][8], cv[2][8], dv0r[2], dv1r[2];
    load8(xb[0], xbp); load8(cv[0], cvp);
    dv0r[0] = dvp[d0]; dv1r[0] = dvp[d0 + 1];

    float p0[8], p1[8];

    for (int g = 0; g < CT / 8; g++) {
        #pragma unroll
        for (int t8 = 0; t8 < 8; t8++) {
            const int t  = g * 8 + t8;
            const int tp = (t + 1 < CT) ? (t + 1) : t;
            const int sp = (t + 1) & 1;
            load8(xb[sp], xbp + (size_t)tp * 256);
            load8(cv[sp], cvp + (size_t)tp * 256);
            dv0r[sp] = dvp[(size_t)tp * 256 + d0];
            dv1r[sp] = dvp[(size_t)tp * 256 + d0 + 1];

            const int sc = t & 1;
            const float dv0 = dv0r[sc];
            const float dv1 = dv1r[sc];
            ds0 += dv0; ds1 += dv1;
            float acc0 = 0.f, acc1 = 0.f;
            #pragma unroll
            for (int j = 0; j < 8; j++) {
                const float bx = xb[sc][j];
                const float cj = cv[sc][j];
                s0[j] = fmaf(ex2f(dv0 * a0[j]), s0[j], dv0 * bx);
                acc0  = fmaf(s0[j], cj, acc0);
                s1[j] = fmaf(ex2f(dv1 * a1[j]), s1[j], dv1 * bx);
                acc1  = fmaf(s1[j], cj, acc1);
            }
            p0[t8] = acc0; p1[t8] = acc1;
        }
        treduce8(p0, lane);
        treduce8(p1, lane);
        if (lane < 8) {
            g_y[(size_t)(row0 + g * 8 + lane) * 256 + d0]     = p0[0];
            g_y[(size_t)(row0 + g * 8 + lane) * 256 + d0 + 1] = p1[0];
        }
    }

    store8(g_state + ((size_t)(c * 4 + b) * 256 + d0)     * 256 + no, s0);
    store8(g_state + ((size_t)(c * 4 + b) * 256 + d0 + 1) * 256 + no, s1);
    if (lane == 0) {
        g_dsum[(c * 4 + b) * 256 + d0]     = ds0;
        g_dsum[(c * 4 + b) * 256 + d0 + 1] = ds1;
    }
}

// ---------------------------------------------------------------------------
// Pass C (m=2, R9 config): prefix combine + correction + SiLU gate.
// Grid (32, NC, 4), 128 threads.
// ---------------------------------------------------------------------------
__global__ void __launch_bounds__(128) scan_passC(const float* __restrict__ A)
{
    const int c    = blockIdx.y;
    const int b    = blockIdx.z;
    const int wid  = threadIdx.x >> 5;
    const int lane = threadIdx.x & 31;
    const int d0   = blockIdx.x * 8 + wid * 2;
    const int no   = lane << 3;
    const float LOG2E = 1.4426950408889634f;

    float a0[8], a1[8];
    load8(a0, A + (size_t)d0 * 256 + no);
    load8(a1, A + (size_t)(d0 + 1) * 256 + no);
    #pragma unroll
    for (int j = 0; j < 8; j++) { a0[j] *= LOG2E; a1[j] *= LOG2E; }

    float w0[8] = {}, w1[8] = {};
    for (int cp = 0; cp < c; cp++) {
        float e0[8], e1[8];
        load8(e0, g_state + ((size_t)(cp * 4 + b) * 256 + d0)     * 256 + no);
        load8(e1, g_state + ((size_t)(cp * 4 + b) * 256 + d0 + 1) * 256 + no);
        const float dsa = g_dsum[(cp * 4 + b) * 256 + d0];
        const float dsb = g_dsum[(cp * 4 + b) * 256 + d0 + 1];
        #pragma unroll
        for (int j = 0; j < 8; j++) {
            w0[j] = fmaf(ex2f(dsa * a0[j]), w0[j], e0[j]);
            w1[j] = fmaf(ex2f(dsb * a1[j]), w1[j], e1[j]);
        }
    }

    const int row0 = b * 512 + c * CT;
    const float* __restrict__ cvp = g_Cv    + (size_t)row0 * 256 + no;
    const float* __restrict__ dvp = g_delta + (size_t)row0 * 256;
    const float* __restrict__ zvp = g_xproj + (size_t)row0 * 512 + 256;
    float*       __restrict__ yp  = g_y     + (size_t)row0 * 256;

    float cv[2][8], dv0r[2], dv1r[2];
    load8(cv[0], cvp);
    dv0r[0] = dvp[d0]; dv1r[0] = dvp[d0 + 1];

    float p0[8], p1[8];

    for (int g = 0; g < CT / 8; g++) {
        const int tg = g * 8 + (lane & 7);
        const float zq0 = zvp[(size_t)tg * 512 + d0];
        const float zq1 = zvp[(size_t)tg * 512 + d0 + 1];
        const float yq0 = yp[(size_t)tg * 256 + d0];
        const float yq1 = yp[(size_t)tg * 256 + d0 + 1];

        #pragma unroll
        for (int t8 = 0; t8 < 8; t8++) {
            const int t  = g * 8 + t8;
            const int tp = (t + 1 < CT) ? (t + 1) : t;
            const int sp = (t + 1) & 1;
            load8(cv[sp], cvp + (size_t)tp * 256);
            dv0r[sp] = dvp[(size_t)tp * 256 + d0];
            dv1r[sp] = dvp[(size_t)tp * 256 + d0 + 1];

            const int sc = t & 1;
            const float dv0 = dv0r[sc];
            const float dv1 = dv1r[sc];
            float acc0 = 0.f, acc1 = 0.f;
            #pragma unroll
            for (int j = 0; j < 8; j++) {
                const float cj = cv[sc][j];
                w0[j] *= ex2f(dv0 * a0[j]);
                acc0 = fmaf(w0[j], cj, acc0);
                w1[j] *= ex2f(dv1 * a1[j]);
                acc1 = fmaf(w1[j], cj, acc1);
            }
            p0[t8] = acc0; p1[t8] = acc1;
        }
        treduce8(p0, lane);
        treduce8(p1, lane);
        if (lane < 8) {
            const float sg0 = 1.f / (1.f + __expf(-zq0));
            const float sg1 = 1.f / (1.f + __expf(-zq1));
            yp[(size_t)(g * 8 + lane) * 256 + d0]     = (yq0 + p0[0]) * (zq0 * sg0);
            yp[(size_t)(g * 8 + lane) * 256 + d0 + 1] = (yq1 + p1[0]) * (zq1 * sg1);
        }
    }
}

extern "C" void kernel_launch(void* const* d_in, const int* in_sizes, int n_in,
                              void* d_out, int out_size)
{
    const float* x       = (const float*)d_in[0];
    const float* W_in    = (const float*)d_in[1];
    const float* W_delta = (const float*)d_in[2];
    const float* W_B     = (const float*)d_in[3];
    const float* W_C     = (const float*)d_in[4];
    const float* W_out   = (const float*)d_in[5];
    const float* A       = (const float*)d_in[6];
    float* out = (float*)d_out;

    k_in_proj <<<dim3(8, 32),     256>>>(x, W_in);
    k_dbc     <<<dim3(4, 32, 3),  256>>>(W_delta, W_B, W_C);
    scan_passA<<<dim3(32, NC, 4), 128>>>(A);
    scan_passC<<<dim3(32, NC, 4), 128>>>(A);
    k_out_proj<<<dim3(2, 64),     128>>>(W_out, out);
}